// round 14
// baseline (speedup 1.0000x reference)
#include <cuda_runtime.h>
#include <math.h>

#define IN_DIM   256
#define OUT_DIM  512
#define MEM_LEN  131072
#define BETA_F   1.0f

#define KB_ENC   64       // matvec blocks (4 W-rows each)
#define NB_MD    4096     // mem_data-stream blocks (256 MB traffic, 64 KB/block)
#define NB_MEM   8192     // memory-stream blocks (512 MB traffic, 64 KB/block)
#define BID_MD0  (1 + KB_ENC)            // 65
#define BID_MEM0 (BID_MD0 + NB_MD)       // 4161
#define NB_TOTAL (BID_MEM0 + NB_MEM)     // 12353

// scratch (no device allocs allowed -> __device__ globals)
// statically initialized for the first run; the last block of every run
// resets them for the next replay (graph-deterministic).
__device__ float        g_partial[KB_ENC * OUT_DIM];
__device__ float        g_enc[OUT_DIM];
__device__ unsigned int g_minbits = 0x7F800000u;
__device__ unsigned int g_pdone   = 0u;
__device__ unsigned int g_ready   = 0u;
__device__ unsigned int g_done    = 0u;

__device__ __forceinline__ unsigned int ld_acq(const unsigned int* p)
{
    unsigned int r;
    asm volatile("ld.acquire.gpu.global.u32 %0, [%1];" : "=r"(r) : "l"(p) : "memory");
    return r;
}
__device__ __forceinline__ void st_rel(unsigned int* p, unsigned int v)
{
    asm volatile("st.release.gpu.global.u32 [%0], %1;" :: "l"(p), "r"(v) : "memory");
}

// ---------------------------------------------------------------------------
// ONE kernel, one graph node.
//   block 0:             spin(g_pdone==64); softmax -> g_enc; g_ready=1
//   blocks 1..64:        partial matvec (4 W-rows each, float4 loads)
//   blocks [65,4160]:    mem_data -> O (shifted +1)          [no enc needed]
//   blocks [4161,12352]: spin(g_ready); memory -> O (shifted +1)
//                        + L1 distance + block min -> atomicMin
//   last finished block: loss write + conditional ring-row overwrite + flag reset
// ---------------------------------------------------------------------------
__global__ void __launch_bounds__(256) k_all(
    const float* __restrict__ mem, const float* __restrict__ md,
    const float* __restrict__ W, const float* __restrict__ b_enc,
    const float* __restrict__ x, const float* __restrict__ mean,
    const float* __restrict__ stdv, const int* __restrict__ count,
    float* __restrict__ O)
{
    int tid = threadIdx.x, lane = tid & 31, wlocal = tid >> 5;
    float4* O4 = (float4*)O;
    __shared__ float  sred[8];
    __shared__ float  enc_s[OUT_DIM];
    __shared__ float  bmin[8];
    __shared__ float  xn[4];
    __shared__ unsigned int s_islast;

    if (blockIdx.x == 0) {
        // ================= softmax (waits for the 64 matvec blocks) ==========
        if (tid == 0) {
            while (ld_acq(&g_pdone) != (unsigned)KB_ENC) __nanosleep(32);
        }
        __syncthreads();

        float l0 = b_enc[tid], l1 = b_enc[tid + 256];
#pragma unroll
        for (int b = 0; b < KB_ENC; b++) {
            l0 += g_partial[b * OUT_DIM + tid];
            l1 += g_partial[b * OUT_DIM + tid + 256];
        }
        float m = fmaxf(l0, l1);
#pragma unroll
        for (int o = 16; o; o >>= 1) m = fmaxf(m, __shfl_xor_sync(0xffffffffu, m, o));
        if (lane == 0) sred[wlocal] = m;
        __syncthreads();
        m = sred[0];
#pragma unroll
        for (int i = 1; i < 8; i++) m = fmaxf(m, sred[i]);
        __syncthreads();
        float s = expf(l0 - m) + expf(l1 - m);
#pragma unroll
        for (int o = 16; o; o >>= 1) s += __shfl_xor_sync(0xffffffffu, s, o);
        if (lane == 0) sred[wlocal] = s;
        __syncthreads();
        s = 0.0f;
#pragma unroll
        for (int i = 0; i < 8; i++) s += sred[i];
        float ls = logf(s);
        g_enc[tid]       = l0 - m - ls;
        g_enc[tid + 256] = l1 - m - ls;
        __threadfence();
        __syncthreads();
        if (tid == 0) st_rel(&g_ready, 1u);
    } else if (blockIdx.x < BID_MD0) {
        // ================= partial matvec (blocks 1..64) =====================
        int row0 = (blockIdx.x - 1) * 4;
        if (tid < 4) {
            int k = row0 + tid;
            float sv = stdv[k];
            xn[tid] = (sv == 0.0f) ? 0.0f : (x[k] - mean[k]) / sv;
        }
        __syncthreads();
        if (tid < 128) {
            const float4* W4 = (const float4*)W;      // row k = 128 float4s
            float4 acc = make_float4(0.f, 0.f, 0.f, 0.f);
#pragma unroll
            for (int r = 0; r < 4; r++) {
                float4 w = W4[(size_t)(row0 + r) * 128 + tid];
                float  sv = xn[r];
                acc.x = fmaf(sv, w.x, acc.x);
                acc.y = fmaf(sv, w.y, acc.y);
                acc.z = fmaf(sv, w.z, acc.z);
                acc.w = fmaf(sv, w.w, acc.w);
            }
            ((float4*)g_partial)[(size_t)(blockIdx.x - 1) * 128 + tid] = acc;
        }
        __threadfence();
        __syncthreads();
        if (tid == 0) atomicAdd(&g_pdone, 1u);
    } else if (blockIdx.x < BID_MEM0) {
        // ================= mem_data stream (no enc dependency) ===============
        const int    N4   = MEM_LEN * (IN_DIM / 4);        // 8388608
        const int    OB4  = MEM_LEN * (OUT_DIM / 4);       // 16777216
        const size_t base = 1ull + (size_t)MEM_LEN * OUT_DIM;

        const float4* md4 = (const float4*)md;
        int wg = (blockIdx.x - BID_MD0) * 8 + wlocal;      // 0 .. NB_MD*8-1
        const int C4 = N4 / (NB_MD * 8);                   // 256 float4 per warp
        int s0 = wg * C4;

        float carry = 0.0f;
        if (lane == 0 && wg > 0) carry = __ldg(&md[(size_t)s0 * 4 - 1]);

        for (int k = 0; k < C4 / 128; k++) {               // 2 iterations
            int ib = s0 + k * 128;
            float4 v[4];
#pragma unroll
            for (int j = 0; j < 4; j++) v[j] = md4[ib + j * 32 + lane];
#pragma unroll
            for (int j = 0; j < 4; j++) {
                float wprev = __shfl_up_sync(0xffffffffu, v[j].w, 1);
                if (lane == 0) wprev = carry;
                int i = ib + j * 32 + lane;
                if (i > 0) {
                    O4[OB4 + i] = make_float4(wprev, v[j].x, v[j].y, v[j].z);
                } else {
                    O[base] = v[j].x; O[base + 1] = v[j].y; O[base + 2] = v[j].z;
                }
                carry = __shfl_sync(0xffffffffu, v[j].w, 31);
            }
        }
        if (wg == NB_MD * 8 - 1 && lane == 0)
            O[base + 4ull * N4 - 1] = carry;               // last mem_data element
    } else {
        // ================= memory stream =====================================
        if (tid == 0) {
            while (!ld_acq(&g_ready)) __nanosleep(64);
        }
        __syncthreads();
        enc_s[tid]       = g_enc[tid];
        enc_s[tid + 256] = g_enc[tid + 256];
        __syncthreads();

        const float4* mem4 = (const float4*)mem;
        const float4* e4p  = (const float4*)enc_s;
        float4 e[4];
#pragma unroll
        for (int j = 0; j < 4; j++) e[j] = e4p[j * 32 + lane];

        int wg = (blockIdx.x - BID_MEM0) * 8 + wlocal;     // 0 .. NB_MEM*8-1
        const int RPW = MEM_LEN / (NB_MEM * 8);            // 2 rows per warp
        int base4 = wg * RPW * 128;

        float carry = 0.0f;
        if (lane == 0 && wg > 0) carry = __ldg(&mem[(size_t)base4 * 4 - 1]);

        float localmin = __int_as_float(0x7f800000);
        for (int r = 0; r < RPW; r++) {
            int rb = base4 + r * 128;
            float4 v[4];
#pragma unroll
            for (int j = 0; j < 4; j++) v[j] = mem4[rb + j * 32 + lane];

            float d = 0.0f;
#pragma unroll
            for (int j = 0; j < 4; j++) {
                d += fabsf(v[j].x - e[j].x) + fabsf(v[j].y - e[j].y) +
                     fabsf(v[j].z - e[j].z) + fabsf(v[j].w - e[j].w);
                float wprev = __shfl_up_sync(0xffffffffu, v[j].w, 1);
                if (lane == 0) wprev = carry;
                int i4 = rb + j * 32 + lane;
                if (i4 > 0) {
                    O4[i4] = make_float4(wprev, v[j].x, v[j].y, v[j].z);
                } else {                                    // O[0] is the loss slot
                    O[1] = v[j].x; O[2] = v[j].y; O[3] = v[j].z;
                }
                carry = __shfl_sync(0xffffffffu, v[j].w, 31);
            }
#pragma unroll
            for (int o = 16; o; o >>= 1) d += __shfl_xor_sync(0xffffffffu, d, o);
            localmin = fminf(localmin, d);
        }
        if (wg == NB_MEM * 8 - 1 && lane == 0)
            O[(size_t)MEM_LEN * OUT_DIM] = carry;           // last memory element

        if (lane == 0) bmin[wlocal] = localmin;
        __syncthreads();
        if (tid == 0) {
            float bm = bmin[0];
#pragma unroll
            for (int i = 1; i < 8; i++) bm = fminf(bm, bmin[i]);
            atomicMin(&g_minbits, __float_as_uint(bm));     // dists >= 0
        }
    }

    // ================= last-block epilogue + flag reset ======================
    __threadfence();
    __syncthreads();
    if (tid == 0) {
        unsigned int old = atomicAdd(&g_done, 1u);
        s_islast = (old == (unsigned)(NB_TOTAL - 1)) ? 1u : 0u;
    }
    __syncthreads();
    if (s_islast) {
        float loss = __uint_as_float(g_minbits);
        if (tid == 0) O[0] = loss;
        if (loss <= BETA_F) {
            int pos = count[0] % MEM_LEN;
            float* Om = O + 1LL + (long long)pos * OUT_DIM;
            Om[tid]       = g_enc[tid];
            Om[tid + 256] = g_enc[tid + 256];
            O[1LL + (long long)MEM_LEN * OUT_DIM + (long long)pos * IN_DIM + tid] = x[tid];
        }
        // reset flags for the next graph replay (run-to-run deterministic)
        if (tid == 0) {
            g_minbits = 0x7F800000u;
            g_pdone   = 0u;
            g_ready   = 0u;
            __threadfence();
            g_done    = 0u;
        }
    }
}

// ---------------------------------------------------------------------------
extern "C" void kernel_launch(void* const* d_in, const int* in_sizes, int n_in,
                              void* d_out, int out_size)
{
    const float* x        = (const float*)d_in[0];
    const float* W_enc    = (const float*)d_in[1];
    const float* b_enc    = (const float*)d_in[2];
    const float* memory   = (const float*)d_in[3];
    const float* mem_data = (const float*)d_in[4];
    const float* mean     = (const float*)d_in[5];
    const float* stdv     = (const float*)d_in[6];
    const int*   count    = (const int*)d_in[n_in - 1];
    float* O = (float*)d_out;

    k_all<<<NB_TOTAL, 256>>>(memory, mem_data, W_enc, b_enc, x, mean, stdv,
                             count, O);
}

// round 16
// speedup vs baseline: 1.1117x; 1.1117x over previous
#include <cuda_runtime.h>
#include <math.h>

#define IN_DIM   256
#define OUT_DIM  512
#define MEM_LEN  131072
#define BETA_F   1.0f

#define NTH      512      // threads per block (16 warps)
#define KB_ENC   64       // matvec blocks (4 W-rows each)
#define NB_MD    1024     // mem_data-stream blocks (16 warps x 512 float4 each)
#define NB_MEM   2048     // memory-stream blocks (16 warps x 4 rows each)
#define BID_MD0  (1 + KB_ENC)            // 65
#define BID_MEM0 (BID_MD0 + NB_MD)       // 1089
#define NB_TOTAL (BID_MEM0 + NB_MEM)     // 3137

// scratch (no device allocs allowed -> __device__ globals)
// statically initialized for the first run; the last block of every run
// resets them for the next replay (graph-deterministic).
__device__ float        g_partial[KB_ENC * OUT_DIM];
__device__ float        g_enc[OUT_DIM];
__device__ unsigned int g_minbits = 0x7F800000u;
__device__ unsigned int g_pdone   = 0u;
__device__ unsigned int g_ready   = 0u;
__device__ unsigned int g_done    = 0u;

__device__ __forceinline__ unsigned int ld_acq(const unsigned int* p)
{
    unsigned int r;
    asm volatile("ld.acquire.gpu.global.u32 %0, [%1];" : "=r"(r) : "l"(p) : "memory");
    return r;
}
__device__ __forceinline__ void st_rel(unsigned int* p, unsigned int v)
{
    asm volatile("st.release.gpu.global.u32 [%0], %1;" :: "l"(p), "r"(v) : "memory");
}

// ---------------------------------------------------------------------------
// ONE kernel, one graph node. 512-thread blocks (16 warps).
//   block 0:            spin(g_pdone==64); softmax -> g_enc; g_ready=1
//   blocks 1..64:       partial matvec (4 W-rows each, float4 loads)
//   blocks [65,1088]:   mem_data -> O (shifted +1)          [no enc needed]
//   blocks [1089,3136]: spin(g_ready); memory -> O (shifted +1)
//                       + L1 distance + block min -> atomicMin
//   last finished block: loss write + conditional ring-row overwrite + flag reset
// ---------------------------------------------------------------------------
__global__ void __launch_bounds__(NTH) k_all(
    const float* __restrict__ mem, const float* __restrict__ md,
    const float* __restrict__ W, const float* __restrict__ b_enc,
    const float* __restrict__ x, const float* __restrict__ mean,
    const float* __restrict__ stdv, const int* __restrict__ count,
    float* __restrict__ O)
{
    int tid = threadIdx.x, lane = tid & 31, wlocal = tid >> 5;   // 16 warps
    float4* O4 = (float4*)O;
    __shared__ float  sred[16];
    __shared__ float  enc_s[OUT_DIM];
    __shared__ float  bmin[16];
    __shared__ float  xn[4];
    __shared__ unsigned int s_islast;

    if (blockIdx.x == 0) {
        // ================= softmax (waits for the 64 matvec blocks) ==========
        if (tid == 0) {
            while (ld_acq(&g_pdone) != (unsigned)KB_ENC) __nanosleep(32);
        }
        __syncthreads();

        float l = b_enc[tid];                     // 1 logit per thread (512)
#pragma unroll
        for (int b = 0; b < KB_ENC; b++)
            l += g_partial[b * OUT_DIM + tid];

        float m = l;
#pragma unroll
        for (int o = 16; o; o >>= 1) m = fmaxf(m, __shfl_xor_sync(0xffffffffu, m, o));
        if (lane == 0) sred[wlocal] = m;
        __syncthreads();
        m = sred[0];
#pragma unroll
        for (int i = 1; i < 16; i++) m = fmaxf(m, sred[i]);
        __syncthreads();
        float s = expf(l - m);
#pragma unroll
        for (int o = 16; o; o >>= 1) s += __shfl_xor_sync(0xffffffffu, s, o);
        if (lane == 0) sred[wlocal] = s;
        __syncthreads();
        s = 0.0f;
#pragma unroll
        for (int i = 0; i < 16; i++) s += sred[i];
        g_enc[tid] = l - m - logf(s);
        __threadfence();
        __syncthreads();
        if (tid == 0) st_rel(&g_ready, 1u);
    } else if (blockIdx.x < BID_MD0) {
        // ================= partial matvec (blocks 1..64) =====================
        int row0 = (blockIdx.x - 1) * 4;
        if (tid < 4) {
            int k = row0 + tid;
            float sv = stdv[k];
            xn[tid] = (sv == 0.0f) ? 0.0f : (x[k] - mean[k]) / sv;
        }
        __syncthreads();
        if (tid < 128) {
            const float4* W4 = (const float4*)W;      // row k = 128 float4s
            float4 acc = make_float4(0.f, 0.f, 0.f, 0.f);
#pragma unroll
            for (int r = 0; r < 4; r++) {
                float4 w = W4[(size_t)(row0 + r) * 128 + tid];
                float  sv = xn[r];
                acc.x = fmaf(sv, w.x, acc.x);
                acc.y = fmaf(sv, w.y, acc.y);
                acc.z = fmaf(sv, w.z, acc.z);
                acc.w = fmaf(sv, w.w, acc.w);
            }
            ((float4*)g_partial)[(size_t)(blockIdx.x - 1) * 128 + tid] = acc;
        }
        __threadfence();
        __syncthreads();
        if (tid == 0) atomicAdd(&g_pdone, 1u);
    } else if (blockIdx.x < BID_MEM0) {
        // ================= mem_data stream (no enc dependency) ===============
        const int    N4   = MEM_LEN * (IN_DIM / 4);        // 8388608
        const int    OB4  = MEM_LEN * (OUT_DIM / 4);       // 16777216
        const size_t base = 1ull + (size_t)MEM_LEN * OUT_DIM;

        const float4* md4 = (const float4*)md;
        int wg = (blockIdx.x - BID_MD0) * 16 + wlocal;     // 0 .. 16383
        const int C4 = N4 / (NB_MD * 16);                  // 512 float4 per warp
        int s0 = wg * C4;

        float carry = 0.0f;
        if (lane == 0 && wg > 0) carry = __ldg(&md[(size_t)s0 * 4 - 1]);

        for (int k = 0; k < C4 / 128; k++) {               // 4 iterations
            int ib = s0 + k * 128;
            float4 v[4];
#pragma unroll
            for (int j = 0; j < 4; j++) v[j] = md4[ib + j * 32 + lane];
#pragma unroll
            for (int j = 0; j < 4; j++) {
                float wprev = __shfl_up_sync(0xffffffffu, v[j].w, 1);
                if (lane == 0) wprev = carry;
                int i = ib + j * 32 + lane;
                if (i > 0) {
                    O4[OB4 + i] = make_float4(wprev, v[j].x, v[j].y, v[j].z);
                } else {
                    O[base] = v[j].x; O[base + 1] = v[j].y; O[base + 2] = v[j].z;
                }
                carry = __shfl_sync(0xffffffffu, v[j].w, 31);
            }
        }
        if (wg == NB_MD * 16 - 1 && lane == 0)
            O[base + 4ull * N4 - 1] = carry;               // last mem_data element
    } else {
        // ================= memory stream =====================================
        if (tid == 0) {
            while (!ld_acq(&g_ready)) __nanosleep(64);
        }
        __syncthreads();
        enc_s[tid] = g_enc[tid];
        __syncthreads();

        const float4* mem4 = (const float4*)mem;
        const float4* e4p  = (const float4*)enc_s;
        float4 e[4];
#pragma unroll
        for (int j = 0; j < 4; j++) e[j] = e4p[j * 32 + lane];

        int wg = (blockIdx.x - BID_MEM0) * 16 + wlocal;    // 0 .. 32767
        const int RPW = MEM_LEN / (NB_MEM * 16);           // 4 rows per warp
        int base4 = wg * RPW * 128;

        float carry = 0.0f;
        if (lane == 0 && wg > 0) carry = __ldg(&mem[(size_t)base4 * 4 - 1]);

        float localmin = __int_as_float(0x7f800000);
        for (int r = 0; r < RPW; r++) {
            int rb = base4 + r * 128;
            float4 v[4];
#pragma unroll
            for (int j = 0; j < 4; j++) v[j] = mem4[rb + j * 32 + lane];

            float d = 0.0f;
#pragma unroll
            for (int j = 0; j < 4; j++) {
                d += fabsf(v[j].x - e[j].x) + fabsf(v[j].y - e[j].y) +
                     fabsf(v[j].z - e[j].z) + fabsf(v[j].w - e[j].w);
                float wprev = __shfl_up_sync(0xffffffffu, v[j].w, 1);
                if (lane == 0) wprev = carry;
                int i4 = rb + j * 32 + lane;
                if (i4 > 0) {
                    O4[i4] = make_float4(wprev, v[j].x, v[j].y, v[j].z);
                } else {                                    // O[0] is the loss slot
                    O[1] = v[j].x; O[2] = v[j].y; O[3] = v[j].z;
                }
                carry = __shfl_sync(0xffffffffu, v[j].w, 31);
            }
#pragma unroll
            for (int o = 16; o; o >>= 1) d += __shfl_xor_sync(0xffffffffu, d, o);
            localmin = fminf(localmin, d);
        }
        if (wg == NB_MEM * 16 - 1 && lane == 0)
            O[(size_t)MEM_LEN * OUT_DIM] = carry;           // last memory element

        if (lane == 0) bmin[wlocal] = localmin;
        __syncthreads();
        if (tid == 0) {
            float bm = bmin[0];
#pragma unroll
            for (int i = 1; i < 16; i++) bm = fminf(bm, bmin[i]);
            atomicMin(&g_minbits, __float_as_uint(bm));     // dists >= 0
        }
    }

    // ================= last-block epilogue + flag reset ======================
    __threadfence();
    __syncthreads();
    if (tid == 0) {
        unsigned int old = atomicAdd(&g_done, 1u);
        s_islast = (old == (unsigned)(NB_TOTAL - 1)) ? 1u : 0u;
    }
    __syncthreads();
    if (s_islast) {
        float loss = __uint_as_float(g_minbits);
        if (tid == 0) O[0] = loss;
        if (loss <= BETA_F) {
            int pos = count[0] % MEM_LEN;
            O[1LL + (long long)pos * OUT_DIM + tid] = g_enc[tid];   // 512 threads
            if (tid < IN_DIM)
                O[1LL + (long long)MEM_LEN * OUT_DIM + (long long)pos * IN_DIM + tid] = x[tid];
        }
        // reset flags for the next graph replay (run-to-run deterministic)
        if (tid == 0) {
            g_minbits = 0x7F800000u;
            g_pdone   = 0u;
            g_ready   = 0u;
            __threadfence();
            g_done    = 0u;
        }
    }
}

// ---------------------------------------------------------------------------
extern "C" void kernel_launch(void* const* d_in, const int* in_sizes, int n_in,
                              void* d_out, int out_size)
{
    const float* x        = (const float*)d_in[0];
    const float* W_enc    = (const float*)d_in[1];
    const float* b_enc    = (const float*)d_in[2];
    const float* memory   = (const float*)d_in[3];
    const float* mem_data = (const float*)d_in[4];
    const float* mean     = (const float*)d_in[5];
    const float* stdv     = (const float*)d_in[6];
    const int*   count    = (const int*)d_in[n_in - 1];
    float* O = (float*)d_out;

    k_all<<<NB_TOTAL, NTH>>>(memory, mem_data, W_enc, b_enc, x, mean, stdv,
                             count, O);
}